// round 13
// baseline (speedup 1.0000x reference)
#include <cuda_runtime.h>
#include <cuda_bf16.h>
#include <math.h>

#define NN 100000
#define EE 1600000
#define DIM 128
#define HEADS 4
#define HC 32

// ---------------- device scratch (allocation-free rule: static globals) ----
__device__ float g_agg[NN * DIM];   // (1+eps)*x + sum relu(x[src]+ea)
__device__ float g_tmp[NN * DIM];   // relu(agg@W1+b1)
__device__ float g_h[NN * DIM];     // LN(relu(.@W2+b2)) + x
__device__ float g_xp[NN * DIM];    // h @ gat_w
__device__ float g_out[NN * DIM];   // GAT weighted aggregation
__device__ float g_asrc[NN * HEADS];
__device__ float g_adst[NN * HEADS];
__device__ float g_wsum[NN * HEADS];

// ---------------- helpers ----------------
__device__ __forceinline__ float4 relu4(float4 v) {
    v.x = fmaxf(v.x, 0.f); v.y = fmaxf(v.y, 0.f);
    v.z = fmaxf(v.z, 0.f); v.w = fmaxf(v.w, 0.f);
    return v;
}

__device__ __forceinline__ void red_add_v4(float* p, float4 v) {
    asm volatile("red.global.add.v4.f32 [%0], {%1,%2,%3,%4};"
                 :: "l"(p), "f"(v.x), "f"(v.y), "f"(v.z), "f"(v.w) : "memory");
}

// ---------------- K1: agg init = (1+eps)*x ----------------
__global__ __launch_bounds__(256) void k_init_agg(const float* __restrict__ x,
                                                  const float* __restrict__ eps) {
    int i = blockIdx.x * 256 + threadIdx.x;        // float4 index, exactly N*DIM/4
    float e = 1.0f + eps[0];
    float4 v = ((const float4*)x)[i];
    v.x *= e; v.y *= e; v.z *= e; v.w *= e;
    ((float4*)g_agg)[i] = v;
}

// ---------------- K2: GINE edge pass (warp per edge) ----------------
__global__ __launch_bounds__(256) void k_gine_edge(const float* __restrict__ x,
                                                   const int* __restrict__ ei,
                                                   const float* __restrict__ ea) {
    int w = (blockIdx.x * 256 + threadIdx.x) >> 5;   // edge id
    int lane = threadIdx.x & 31;
    if (w >= EE) return;
    int s = ei[w];
    int d = ei[EE + w];
    float4 xv = __ldg(&((const float4*)x)[(size_t)s * 32 + lane]);
    float4 ev = __ldg(&((const float4*)ea)[(size_t)w * 32 + lane]);
    float4 m;
    m.x = fmaxf(xv.x + ev.x, 0.f);
    m.y = fmaxf(xv.y + ev.y, 0.f);
    m.z = fmaxf(xv.z + ev.z, 0.f);
    m.w = fmaxf(xv.w + ev.w, 0.f);
    red_add_v4(g_agg + (size_t)d * DIM + lane * 4, m);
}

// ---------------- K3: 128x128 SGEMM, 64-row tile, fused epilogues ----------
// EPI 0: out = relu(in@W + b)
// EPI 1: out = LN(relu(in@W + b); p0=g, p1=b) + p2(resid)
// EPI 2: out = in@W (xp); q0/q1 = per-head dot with p0=att_src / p1=att_dst
template <int EPI>
__global__ __launch_bounds__(256) void k_gemm128(
    const float* __restrict__ in, const float* __restrict__ W,
    const float* __restrict__ bias, float* __restrict__ out, int n,
    const float* __restrict__ p0, const float* __restrict__ p1,
    const float* __restrict__ p2, float* __restrict__ q0, float* __restrict__ q1) {
    extern __shared__ float smem[];
    float* Ws = smem;                 // 128*128
    float* Is = smem + DIM * DIM;     // 64*128
    float4* Ws4 = (float4*)Ws;
    float4* Is4 = (float4*)Is;

    const int t = threadIdx.x;
    const int row0 = blockIdx.x * 64;

    // stage W (16384 floats = 4096 float4)
    #pragma unroll
    for (int i = 0; i < 16; i++) Ws4[t + 256 * i] = ((const float4*)W)[t + 256 * i];
    // stage input tile (64 rows x 128 = 2048 float4)
    #pragma unroll
    for (int i = 0; i < 8; i++) {
        int idx = t + 256 * i;
        int r = idx >> 5;
        Is4[idx] = (row0 + r < n) ? ((const float4*)in)[(size_t)(row0 + r) * 32 + (idx & 31)]
                                  : make_float4(0.f, 0.f, 0.f, 0.f);
    }
    __syncthreads();

    const int tx = t & 31;    // column group (4 cols)
    const int ty = t >> 5;    // row group (8 rows)
    float acc[8][4];
    float4 bv = bias ? ((const float4*)bias)[tx] : make_float4(0.f, 0.f, 0.f, 0.f);
    #pragma unroll
    for (int r = 0; r < 8; r++) {
        acc[r][0] = bv.x; acc[r][1] = bv.y; acc[r][2] = bv.z; acc[r][3] = bv.w;
    }

    #pragma unroll 4
    for (int k = 0; k < DIM; k++) {
        float4 w4 = Ws4[k * 32 + tx];
        #pragma unroll
        for (int r = 0; r < 8; r++) {
            float a = Is[(ty * 8 + r) * DIM + k];
            acc[r][0] = fmaf(a, w4.x, acc[r][0]);
            acc[r][1] = fmaf(a, w4.y, acc[r][1]);
            acc[r][2] = fmaf(a, w4.z, acc[r][2]);
            acc[r][3] = fmaf(a, w4.w, acc[r][3]);
        }
    }

    if (EPI == 0) {
        #pragma unroll
        for (int r = 0; r < 8; r++) {
            int row = row0 + ty * 8 + r;
            if (row < n) {
                float4 v = make_float4(acc[r][0], acc[r][1], acc[r][2], acc[r][3]);
                ((float4*)out)[(size_t)row * 32 + tx] = relu4(v);
            }
        }
        return;
    }

    // write result tile back to shared for row-wise epilogues
    __syncthreads();
    #pragma unroll
    for (int r = 0; r < 8; r++)
        Is4[(ty * 8 + r) * 32 + tx] = make_float4(acc[r][0], acc[r][1], acc[r][2], acc[r][3]);
    __syncthreads();

    const int lane = t & 31;
    const int wid = t >> 5;
    #pragma unroll
    for (int rr = 0; rr < 8; rr++) {
        int r = wid * 8 + rr;
        int row = row0 + r;
        if (row >= n) break;
        float4 v = Is4[r * 32 + lane];

        if (EPI == 1) {
            v = relu4(v);
            float s = v.x + v.y + v.z + v.w;
            #pragma unroll
            for (int o = 16; o; o >>= 1) s += __shfl_xor_sync(0xffffffffu, s, o);
            float mu = s * (1.0f / DIM);
            float dx = v.x - mu, dy = v.y - mu, dz = v.z - mu, dw = v.w - mu;
            float ss = dx * dx + dy * dy + dz * dz + dw * dw;
            #pragma unroll
            for (int o = 16; o; o >>= 1) ss += __shfl_xor_sync(0xffffffffu, ss, o);
            float inv = rsqrtf(ss * (1.0f / DIM) + 1e-5f);
            float4 g = ((const float4*)p0)[lane];
            float4 b = ((const float4*)p1)[lane];
            float4 res = ((const float4*)p2)[(size_t)row * 32 + lane];
            float4 o4;
            o4.x = dx * inv * g.x + b.x + res.x;
            o4.y = dy * inv * g.y + b.y + res.y;
            o4.z = dz * inv * g.z + b.z + res.z;
            o4.w = dw * inv * g.w + b.w + res.w;
            ((float4*)out)[(size_t)row * 32 + lane] = o4;
        } else {  // EPI == 2: xp + attention coefficients
            ((float4*)out)[(size_t)row * 32 + lane] = v;
            float4 as = ((const float4*)p0)[lane];   // att_src flat [128]
            float4 ad = ((const float4*)p1)[lane];   // att_dst flat [128]
            float ps = v.x * as.x + v.y * as.y + v.z * as.z + v.w * as.w;
            float pd = v.x * ad.x + v.y * ad.y + v.z * ad.z + v.w * ad.w;
            #pragma unroll
            for (int o = 4; o; o >>= 1) {
                ps += __shfl_down_sync(0xffffffffu, ps, o, 8);
                pd += __shfl_down_sync(0xffffffffu, pd, o, 8);
            }
            if ((lane & 7) == 0) {
                q0[row * HEADS + (lane >> 3)] = ps;
                q1[row * HEADS + (lane >> 3)] = pd;
            }
        }
    }
}

// ---------------- K4: GAT self-loop init (warp per node) ----------------
__global__ __launch_bounds__(256) void k_gat_init() {
    int node = (blockIdx.x * 256 + threadIdx.x) >> 5;
    int lane = threadIdx.x & 31;
    if (node >= NN) return;
    float aw = 0.f;
    if (lane < HEADS) {
        float l = g_asrc[node * HEADS + lane] + g_adst[node * HEADS + lane];
        l = (l > 0.f) ? l : 0.2f * l;
        aw = expf(l);
        g_wsum[node * HEADS + lane] = aw;
    }
    float w = __shfl_sync(0xffffffffu, aw, lane >> 3);
    float4 v = ((const float4*)g_xp)[(size_t)node * 32 + lane];
    ((float4*)g_out)[(size_t)node * 32 + lane] =
        make_float4(w * v.x, w * v.y, w * v.z, w * v.w);
}

// ---------------- K5: GAT edge pass (warp per edge, fused softmax-sum+agg) --
__global__ __launch_bounds__(256) void k_gat_edge(const int* __restrict__ ei) {
    int e = (blockIdx.x * 256 + threadIdx.x) >> 5;
    int lane = threadIdx.x & 31;
    if (e >= EE) return;
    int s = ei[e];
    int d = ei[EE + e];
    float aw = 0.f;
    if (lane < HEADS) {
        float l = g_asrc[s * HEADS + lane] + g_adst[d * HEADS + lane];
        l = (l > 0.f) ? l : 0.2f * l;
        aw = expf(l);
        atomicAdd(&g_wsum[d * HEADS + lane], aw);
    }
    float w = __shfl_sync(0xffffffffu, aw, lane >> 3);
    float4 v = __ldg(&((const float4*)g_xp)[(size_t)s * 32 + lane]);
    red_add_v4(g_out + (size_t)d * DIM + lane * 4,
               make_float4(w * v.x, w * v.y, w * v.z, w * v.w));
}

// ---------------- K6: final epilogue (warp per node) ----------------
__global__ __launch_bounds__(256) void k_final(const float* __restrict__ gat_b,
                                               const float* __restrict__ ln2_g,
                                               const float* __restrict__ ln2_b,
                                               float* __restrict__ outp) {
    int node = (blockIdx.x * 256 + threadIdx.x) >> 5;
    int lane = threadIdx.x & 31;
    if (node >= NN) return;
    float4 v = ((const float4*)g_out)[(size_t)node * 32 + lane];
    float ws = g_wsum[node * HEADS + (lane >> 3)] + 1e-16f;
    float inv_s = 1.0f / ws;
    float4 gb = ((const float4*)gat_b)[lane];
    v.x = fmaxf(v.x * inv_s + gb.x, 0.f);
    v.y = fmaxf(v.y * inv_s + gb.y, 0.f);
    v.z = fmaxf(v.z * inv_s + gb.z, 0.f);
    v.w = fmaxf(v.w * inv_s + gb.w, 0.f);
    float s = v.x + v.y + v.z + v.w;
    #pragma unroll
    for (int o = 16; o; o >>= 1) s += __shfl_xor_sync(0xffffffffu, s, o);
    float mu = s * (1.0f / DIM);
    float dx = v.x - mu, dy = v.y - mu, dz = v.z - mu, dw = v.w - mu;
    float ss = dx * dx + dy * dy + dz * dz + dw * dw;
    #pragma unroll
    for (int o = 16; o; o >>= 1) ss += __shfl_xor_sync(0xffffffffu, ss, o);
    float inv = rsqrtf(ss * (1.0f / DIM) + 1e-5f);
    float4 g = ((const float4*)ln2_g)[lane];
    float4 b = ((const float4*)ln2_b)[lane];
    float4 h = ((const float4*)g_h)[(size_t)node * 32 + lane];
    float4 o4;
    o4.x = dx * inv * g.x + b.x + h.x;
    o4.y = dy * inv * g.y + b.y + h.y;
    o4.z = dz * inv * g.z + b.z + h.z;
    o4.w = dw * inv * g.w + b.w + h.w;
    ((float4*)outp)[(size_t)node * 32 + lane] = o4;
}

// ---------------- launch ----------------
extern "C" void kernel_launch(void* const* d_in, const int* in_sizes, int n_in,
                              void* d_out, int out_size) {
    const float* x      = (const float*)d_in[0];
    const int*   ei     = (const int*)d_in[1];
    const float* ea     = (const float*)d_in[2];
    const float* eps    = (const float*)d_in[3];
    const float* w1     = (const float*)d_in[4];
    const float* b1     = (const float*)d_in[5];
    const float* w2     = (const float*)d_in[6];
    const float* b2     = (const float*)d_in[7];
    const float* ln1_g  = (const float*)d_in[8];
    const float* ln1_b  = (const float*)d_in[9];
    const float* gat_w  = (const float*)d_in[10];
    const float* att_s  = (const float*)d_in[11];
    const float* att_d  = (const float*)d_in[12];
    const float* gat_b  = (const float*)d_in[13];
    const float* ln2_g  = (const float*)d_in[14];
    const float* ln2_b  = (const float*)d_in[15];
    float* outp = (float*)d_out;

    const int smem = (DIM * DIM + 64 * DIM) * (int)sizeof(float);  // 96 KB
    cudaFuncSetAttribute(k_gemm128<0>, cudaFuncAttributeMaxDynamicSharedMemorySize, smem);
    cudaFuncSetAttribute(k_gemm128<1>, cudaFuncAttributeMaxDynamicSharedMemorySize, smem);
    cudaFuncSetAttribute(k_gemm128<2>, cudaFuncAttributeMaxDynamicSharedMemorySize, smem);

    float* agg = nullptr; cudaGetSymbolAddress((void**)&agg, g_agg);
    float* tmp = nullptr; cudaGetSymbolAddress((void**)&tmp, g_tmp);
    float* h   = nullptr; cudaGetSymbolAddress((void**)&h, g_h);
    float* xp  = nullptr; cudaGetSymbolAddress((void**)&xp, g_xp);
    float* asrc= nullptr; cudaGetSymbolAddress((void**)&asrc, g_asrc);
    float* adst= nullptr; cudaGetSymbolAddress((void**)&adst, g_adst);

    const int edge_blocks = EE / 8;               // 200000 (warp per edge)
    const int node_blocks = (NN + 7) / 8;         // 12500  (warp per node)
    const int vec_blocks  = (NN * DIM / 4) / 256; // 12500

    k_init_agg<<<vec_blocks, 256>>>(x, eps);
    k_gine_edge<<<edge_blocks, 256>>>(x, ei, ea);

    const int gblocks = (NN + 63) / 64;
    k_gemm128<0><<<gblocks, 256, smem>>>(agg, w1, b1, tmp, NN,
                                         nullptr, nullptr, nullptr, nullptr, nullptr);
    k_gemm128<1><<<gblocks, 256, smem>>>(tmp, w2, b2, h, NN,
                                         ln1_g, ln1_b, x, nullptr, nullptr);
    k_gemm128<2><<<gblocks, 256, smem>>>(h, gat_w, nullptr, xp, NN,
                                         att_s, att_d, nullptr, asrc, adst);

    k_gat_init<<<node_blocks, 256>>>();
    k_gat_edge<<<edge_blocks, 256>>>(ei);
    k_final<<<node_blocks, 256>>>(gat_b, ln2_g, ln2_b, outp);
}

// round 14
// speedup vs baseline: 1.5737x; 1.5737x over previous
#include <cuda_runtime.h>
#include <cuda_bf16.h>
#include <math.h>

#define NN 100000
#define EE 1600000
#define DIM 128
#define HEADS 4
#define HC 32

// ---------------- device scratch ----------------
__device__ float g_agg[NN * DIM];   // (1+eps)*x + sum relu(x[src]+ea)
__device__ float g_h[NN * DIM];     // LN1(relu(MLP)) + x
__device__ float g_xp[NN * DIM];    // h @ gat_w
__device__ float g_asrc[NN * HEADS];
__device__ float g_adst[NN * HEADS];

// CSR by dst
__device__ int g_deg[NN];
__device__ int g_off[NN + 1];
__device__ int g_cursor[NN];
__device__ int g_bsum[128];
__device__ int g_boff[128];
__device__ int g_src_sorted[EE];
__device__ int g_eid_sorted[EE];

// ---------------- CSR build ----------------
__global__ __launch_bounds__(1024) void k_zero_deg() {
    int g = blockIdx.x * 1024 + threadIdx.x;
    if (g < NN) g_deg[g] = 0;
}

__global__ __launch_bounds__(256) void k_hist(const int* __restrict__ ei) {
    int e = blockIdx.x * 256 + threadIdx.x;   // grid sized exactly EE/256
    atomicAdd(&g_deg[ei[EE + e]], 1);
}

__global__ __launch_bounds__(1024) void k_scan1() {
    __shared__ int s[1024];
    int tid = threadIdx.x;
    int g = blockIdx.x * 1024 + tid;
    int v = (g < NN) ? g_deg[g] : 0;
    s[tid] = v;
    __syncthreads();
    #pragma unroll
    for (int off = 1; off < 1024; off <<= 1) {
        int t = (tid >= off) ? s[tid - off] : 0;
        __syncthreads();
        s[tid] += t;
        __syncthreads();
    }
    if (g < NN) g_off[g] = s[tid] - v;          // exclusive, block-local
    if (tid == 1023) g_bsum[blockIdx.x] = s[1023];
}

__global__ __launch_bounds__(128) void k_scan2(int nb) {
    __shared__ int s[128];
    int tid = threadIdx.x;
    int v = (tid < nb) ? g_bsum[tid] : 0;
    s[tid] = v;
    __syncthreads();
    #pragma unroll
    for (int off = 1; off < 128; off <<= 1) {
        int t = (tid >= off) ? s[tid - off] : 0;
        __syncthreads();
        s[tid] += t;
        __syncthreads();
    }
    if (tid < nb) g_boff[tid] = s[tid] - v;     // exclusive
}

__global__ __launch_bounds__(1024) void k_scan3() {
    int g = blockIdx.x * 1024 + threadIdx.x;
    if (g < NN) {
        int o = g_off[g] + g_boff[blockIdx.x];
        g_off[g] = o;
        g_cursor[g] = o;
    }
    if (g == 0) g_off[NN] = EE;
}

__global__ __launch_bounds__(256) void k_scatter(const int* __restrict__ ei) {
    int e = blockIdx.x * 256 + threadIdx.x;
    int d = ei[EE + e];
    int pos = atomicAdd(&g_cursor[d], 1);
    g_src_sorted[pos] = ei[e];
    g_eid_sorted[pos] = e;
}

// ---------------- GINE gather: warp per node, no atomics ----------------
__global__ __launch_bounds__(256) void k_gine_gather(const float* __restrict__ x,
                                                     const float* __restrict__ ea,
                                                     const float* __restrict__ eps) {
    int node = (blockIdx.x * 256 + threadIdx.x) >> 5;
    int lane = threadIdx.x & 31;
    if (node >= NN) return;
    const float4* x4 = (const float4*)x;
    const float4* ea4 = (const float4*)ea;

    float e1 = 1.0f + eps[0];
    float4 acc = x4[(size_t)node * 32 + lane];
    acc.x *= e1; acc.y *= e1; acc.z *= e1; acc.w *= e1;

    int o0 = g_off[node], o1 = g_off[node + 1];
    for (int base = o0; base < o1; base += 32) {
        int rem = o1 - base;
        int m = rem < 32 ? rem : 32;
        int sj = 0, ej = 0;
        if (lane < m) { sj = g_src_sorted[base + lane]; ej = g_eid_sorted[base + lane]; }
        for (int j = 0; j < m; j++) {
            int s = __shfl_sync(0xffffffffu, sj, j);
            int e = __shfl_sync(0xffffffffu, ej, j);
            float4 xs = __ldg(&x4[(size_t)s * 32 + lane]);
            float4 ev = __ldg(&ea4[(size_t)e * 32 + lane]);
            acc.x += fmaxf(xs.x + ev.x, 0.f);
            acc.y += fmaxf(xs.y + ev.y, 0.f);
            acc.z += fmaxf(xs.z + ev.z, 0.f);
            acc.w += fmaxf(xs.w + ev.w, 0.f);
        }
    }
    ((float4*)g_agg)[(size_t)node * 32 + lane] = acc;
}

// ---------------- fused 3-stage GEMM (MLP + LN1 + gat_w projection) -------
__device__ __forceinline__ void gemm_tile(float acc[8][4], const float4* Is4,
                                          const float4* Ws4, int tx, int ty) {
    #pragma unroll 4
    for (int k4 = 0; k4 < 32; k4++) {
        float4 w0 = Ws4[(4 * k4 + 0) * 32 + tx];
        float4 w1 = Ws4[(4 * k4 + 1) * 32 + tx];
        float4 w2 = Ws4[(4 * k4 + 2) * 32 + tx];
        float4 w3 = Ws4[(4 * k4 + 3) * 32 + tx];
        #pragma unroll
        for (int r = 0; r < 8; r++) {
            float4 a = Is4[(ty * 8 + r) * 32 + k4];
            acc[r][0] = fmaf(a.x, w0.x, fmaf(a.y, w1.x, fmaf(a.z, w2.x, fmaf(a.w, w3.x, acc[r][0]))));
            acc[r][1] = fmaf(a.x, w0.y, fmaf(a.y, w1.y, fmaf(a.z, w2.y, fmaf(a.w, w3.y, acc[r][1]))));
            acc[r][2] = fmaf(a.x, w0.z, fmaf(a.y, w1.z, fmaf(a.z, w2.z, fmaf(a.w, w3.z, acc[r][2]))));
            acc[r][3] = fmaf(a.x, w0.w, fmaf(a.y, w1.w, fmaf(a.z, w2.w, fmaf(a.w, w3.w, acc[r][3]))));
        }
    }
}

__global__ __launch_bounds__(256) void k_fused_gemm(
    const float* __restrict__ x,
    const float* __restrict__ w1, const float* __restrict__ b1,
    const float* __restrict__ w2, const float* __restrict__ b2,
    const float* __restrict__ ln1g, const float* __restrict__ ln1b,
    const float* __restrict__ gatw,
    const float* __restrict__ atts, const float* __restrict__ attd) {
    extern __shared__ float smem[];
    float4* Ws4 = (float4*)smem;                  // 128x128 = 64KB
    float4* Is4 = (float4*)(smem + DIM * DIM);    // 64x128  = 32KB

    const int t = threadIdx.x;
    const int row0 = blockIdx.x * 64;
    const int tx = t & 31;
    const int ty = t >> 5;

    // ---- stage W1 + input tile (g_agg) ----
    #pragma unroll
    for (int i = 0; i < 16; i++) Ws4[t + 256 * i] = ((const float4*)w1)[t + 256 * i];
    #pragma unroll
    for (int i = 0; i < 8; i++) {
        int idx = t + 256 * i;
        int r = idx >> 5;
        Is4[idx] = (row0 + r < NN) ? ((const float4*)g_agg)[(size_t)(row0 + r) * 32 + (idx & 31)]
                                   : make_float4(0.f, 0.f, 0.f, 0.f);
    }
    __syncthreads();

    float acc[8][4];
    // ---- GEMM1: relu(agg@W1 + b1) ----
    {
        float4 bv = ((const float4*)b1)[tx];
        #pragma unroll
        for (int r = 0; r < 8; r++) { acc[r][0]=bv.x; acc[r][1]=bv.y; acc[r][2]=bv.z; acc[r][3]=bv.w; }
    }
    gemm_tile(acc, Is4, Ws4, tx, ty);
    __syncthreads();   // everyone done reading W1 / input tile
    #pragma unroll
    for (int r = 0; r < 8; r++)
        Is4[(ty * 8 + r) * 32 + tx] = make_float4(fmaxf(acc[r][0], 0.f), fmaxf(acc[r][1], 0.f),
                                                  fmaxf(acc[r][2], 0.f), fmaxf(acc[r][3], 0.f));
    #pragma unroll
    for (int i = 0; i < 16; i++) Ws4[t + 256 * i] = ((const float4*)w2)[t + 256 * i];
    __syncthreads();

    // ---- GEMM2: .@W2 + b2, then relu -> LN1 -> +x, write g_h, keep in Is ----
    {
        float4 bv = ((const float4*)b2)[tx];
        #pragma unroll
        for (int r = 0; r < 8; r++) { acc[r][0]=bv.x; acc[r][1]=bv.y; acc[r][2]=bv.z; acc[r][3]=bv.w; }
    }
    gemm_tile(acc, Is4, Ws4, tx, ty);
    {
        float4 g = ((const float4*)ln1g)[tx];
        float4 bb = ((const float4*)ln1b)[tx];
        #pragma unroll
        for (int r = 0; r < 8; r++) {
            int row = row0 + ty * 8 + r;
            float4 v = make_float4(fmaxf(acc[r][0], 0.f), fmaxf(acc[r][1], 0.f),
                                   fmaxf(acc[r][2], 0.f), fmaxf(acc[r][3], 0.f));
            float s = v.x + v.y + v.z + v.w;
            #pragma unroll
            for (int o = 16; o; o >>= 1) s += __shfl_xor_sync(0xffffffffu, s, o);
            float mu = s * (1.0f / DIM);
            float dx = v.x - mu, dy = v.y - mu, dz = v.z - mu, dw = v.w - mu;
            float ss = dx * dx + dy * dy + dz * dz + dw * dw;
            #pragma unroll
            for (int o = 16; o; o >>= 1) ss += __shfl_xor_sync(0xffffffffu, ss, o);
            float inv = rsqrtf(ss * (1.0f / DIM) + 1e-5f);
            float4 res = (row < NN) ? ((const float4*)x)[(size_t)row * 32 + tx]
                                    : make_float4(0.f, 0.f, 0.f, 0.f);
            float4 o4;
            o4.x = dx * inv * g.x + bb.x + res.x;
            o4.y = dy * inv * g.y + bb.y + res.y;
            o4.z = dz * inv * g.z + bb.z + res.z;
            o4.w = dw * inv * g.w + bb.w + res.w;
            if (row < NN) ((float4*)g_h)[(size_t)row * 32 + tx] = o4;
            Is4[(ty * 8 + r) * 32 + tx] = o4;   // warp-private rows: no sync needed
        }
    }
    __syncthreads();   // everyone done reading W2
    #pragma unroll
    for (int i = 0; i < 16; i++) Ws4[t + 256 * i] = ((const float4*)gatw)[t + 256 * i];
    __syncthreads();

    // ---- GEMM3: h@gat_w -> xp + attention coefficients ----
    #pragma unroll
    for (int r = 0; r < 8; r++) { acc[r][0]=0.f; acc[r][1]=0.f; acc[r][2]=0.f; acc[r][3]=0.f; }
    gemm_tile(acc, Is4, Ws4, tx, ty);
    {
        float4 as = ((const float4*)atts)[tx];
        float4 ad = ((const float4*)attd)[tx];
        #pragma unroll
        for (int r = 0; r < 8; r++) {
            int row = row0 + ty * 8 + r;
            float4 v = make_float4(acc[r][0], acc[r][1], acc[r][2], acc[r][3]);
            float ps = v.x * as.x + v.y * as.y + v.z * as.z + v.w * as.w;
            float pd = v.x * ad.x + v.y * ad.y + v.z * ad.z + v.w * ad.w;
            #pragma unroll
            for (int o = 4; o; o >>= 1) {
                ps += __shfl_down_sync(0xffffffffu, ps, o, 8);
                pd += __shfl_down_sync(0xffffffffu, pd, o, 8);
            }
            if (row < NN) {
                ((float4*)g_xp)[(size_t)row * 32 + tx] = v;
                if ((tx & 7) == 0) {
                    g_asrc[row * HEADS + (tx >> 3)] = ps;
                    g_adst[row * HEADS + (tx >> 3)] = pd;
                }
            }
        }
    }
}

// ---------------- GAT gather: warp per node, fused softmax+norm+LN2+resid --
__global__ __launch_bounds__(256) void k_gat_gather(const float* __restrict__ gat_b,
                                                    const float* __restrict__ ln2g,
                                                    const float* __restrict__ ln2b,
                                                    float* __restrict__ outp) {
    int node = (blockIdx.x * 256 + threadIdx.x) >> 5;
    int lane = threadIdx.x & 31;
    if (node >= NN) return;
    const float4* xp4 = (const float4*)g_xp;
    int h = lane >> 3;

    float adst_d = g_adst[node * HEADS + h];
    // self loop
    float l = g_asrc[node * HEADS + h] + adst_d;
    l = (l > 0.f) ? l : 0.2f * l;
    float w = __expf(l);
    float wsum = w;
    float4 xv = xp4[(size_t)node * 32 + lane];
    float4 acc = make_float4(w * xv.x, w * xv.y, w * xv.z, w * xv.w);

    int o0 = g_off[node], o1 = g_off[node + 1];
    for (int base = o0; base < o1; base += 32) {
        int rem = o1 - base;
        int m = rem < 32 ? rem : 32;
        int sj = 0;
        if (lane < m) sj = g_src_sorted[base + lane];
        for (int j = 0; j < m; j++) {
            int s = __shfl_sync(0xffffffffu, sj, j);
            float l2 = g_asrc[s * HEADS + h] + adst_d;
            l2 = (l2 > 0.f) ? l2 : 0.2f * l2;
            float aw = __expf(l2);
            wsum += aw;
            float4 v = __ldg(&xp4[(size_t)s * 32 + lane]);
            acc.x = fmaf(aw, v.x, acc.x);
            acc.y = fmaf(aw, v.y, acc.y);
            acc.z = fmaf(aw, v.z, acc.z);
            acc.w = fmaf(aw, v.w, acc.w);
        }
    }

    float inv_s = 1.0f / (wsum + 1e-16f);
    float4 gb = ((const float4*)gat_b)[lane];
    float4 v;
    v.x = fmaxf(acc.x * inv_s + gb.x, 0.f);
    v.y = fmaxf(acc.y * inv_s + gb.y, 0.f);
    v.z = fmaxf(acc.z * inv_s + gb.z, 0.f);
    v.w = fmaxf(acc.w * inv_s + gb.w, 0.f);
    float s = v.x + v.y + v.z + v.w;
    #pragma unroll
    for (int o = 16; o; o >>= 1) s += __shfl_xor_sync(0xffffffffu, s, o);
    float mu = s * (1.0f / DIM);
    float dx = v.x - mu, dy = v.y - mu, dz = v.z - mu, dw = v.w - mu;
    float ss = dx * dx + dy * dy + dz * dz + dw * dw;
    #pragma unroll
    for (int o = 16; o; o >>= 1) ss += __shfl_xor_sync(0xffffffffu, ss, o);
    float inv = rsqrtf(ss * (1.0f / DIM) + 1e-5f);
    float4 g = ((const float4*)ln2g)[lane];
    float4 b = ((const float4*)ln2b)[lane];
    float4 hres = ((const float4*)g_h)[(size_t)node * 32 + lane];
    float4 o4;
    o4.x = dx * inv * g.x + b.x + hres.x;
    o4.y = dy * inv * g.y + b.y + hres.y;
    o4.z = dz * inv * g.z + b.z + hres.z;
    o4.w = dw * inv * g.w + b.w + hres.w;
    ((float4*)outp)[(size_t)node * 32 + lane] = o4;
}

// ---------------- launch ----------------
extern "C" void kernel_launch(void* const* d_in, const int* in_sizes, int n_in,
                              void* d_out, int out_size) {
    const float* x      = (const float*)d_in[0];
    const int*   ei     = (const int*)d_in[1];
    const float* ea     = (const float*)d_in[2];
    const float* eps    = (const float*)d_in[3];
    const float* w1     = (const float*)d_in[4];
    const float* b1     = (const float*)d_in[5];
    const float* w2     = (const float*)d_in[6];
    const float* b2     = (const float*)d_in[7];
    const float* ln1_g  = (const float*)d_in[8];
    const float* ln1_b  = (const float*)d_in[9];
    const float* gat_w  = (const float*)d_in[10];
    const float* att_s  = (const float*)d_in[11];
    const float* att_d  = (const float*)d_in[12];
    const float* gat_b  = (const float*)d_in[13];
    const float* ln2_g  = (const float*)d_in[14];
    const float* ln2_b  = (const float*)d_in[15];
    float* outp = (float*)d_out;

    const int smem = (DIM * DIM + 64 * DIM) * (int)sizeof(float);  // 96 KB
    cudaFuncSetAttribute(k_fused_gemm, cudaFuncAttributeMaxDynamicSharedMemorySize, smem);

    const int scan_blocks = (NN + 1023) / 1024;   // 98
    const int edge_blocks = EE / 256;             // 6250
    const int node_blocks = (NN * 32) / 256;      // 12500
    const int gemm_blocks = (NN + 63) / 64;       // 1563

    // CSR build (by dst)
    k_zero_deg<<<scan_blocks, 1024>>>();
    k_hist<<<edge_blocks, 256>>>(ei);
    k_scan1<<<scan_blocks, 1024>>>();
    k_scan2<<<1, 128>>>(scan_blocks);
    k_scan3<<<scan_blocks, 1024>>>();
    k_scatter<<<edge_blocks, 256>>>(ei);

    // GINE aggregation (gather, fused (1+eps)*x)
    k_gine_gather<<<node_blocks, 256>>>(x, ea, eps);

    // MLP + LN1 + residual + gat projection + attention coefficients
    k_fused_gemm<<<gemm_blocks, 256, smem>>>(x, w1, b1, w2, b2,
                                             ln1_g, ln1_b, gat_w, att_s, att_d);

    // GAT aggregation (gather, fused softmax + bias + relu + LN2 + residual)
    k_gat_gather<<<node_blocks, 256>>>(gat_b, ln2_g, ln2_b, outp);
}

// round 15
// speedup vs baseline: 1.6146x; 1.0260x over previous
#include <cuda_runtime.h>
#include <cuda_bf16.h>
#include <math.h>
#include <stdint.h>

#define NN 100000
#define EE 1600000
#define DIM 128
#define HEADS 4
#define HC 32

// ---------------- device scratch ----------------
__device__ float g_agg[NN * DIM];   // (1+eps)*x + sum relu(x[src]+ea)
__device__ float g_h[NN * DIM];     // LN1(relu(MLP)) + x
__device__ float g_xp[NN * DIM];    // h @ gat_w
__device__ float g_asrc[NN * HEADS];
__device__ float g_adst[NN * HEADS];

// CSR by dst
__device__ int g_deg[NN];
__device__ int g_off[NN + 1];
__device__ int g_cursor[NN];
__device__ int g_bsum[128];
__device__ int g_boff[128];
__device__ int g_src_sorted[EE];
__device__ int g_eid_sorted[EE];

// ---------------- CSR build ----------------
__global__ __launch_bounds__(1024) void k_zero_deg() {
    int g = blockIdx.x * 1024 + threadIdx.x;
    if (g < NN) g_deg[g] = 0;
}

__global__ __launch_bounds__(256) void k_hist(const int* __restrict__ ei) {
    int e = blockIdx.x * 256 + threadIdx.x;   // grid sized exactly EE/256
    atomicAdd(&g_deg[ei[EE + e]], 1);
}

__global__ __launch_bounds__(1024) void k_scan1() {
    __shared__ int s[1024];
    int tid = threadIdx.x;
    int g = blockIdx.x * 1024 + tid;
    int v = (g < NN) ? g_deg[g] : 0;
    s[tid] = v;
    __syncthreads();
    #pragma unroll
    for (int off = 1; off < 1024; off <<= 1) {
        int t = (tid >= off) ? s[tid - off] : 0;
        __syncthreads();
        s[tid] += t;
        __syncthreads();
    }
    if (g < NN) g_off[g] = s[tid] - v;          // exclusive, block-local
    if (tid == 1023) g_bsum[blockIdx.x] = s[1023];
}

__global__ __launch_bounds__(128) void k_scan2(int nb) {
    __shared__ int s[128];
    int tid = threadIdx.x;
    int v = (tid < nb) ? g_bsum[tid] : 0;
    s[tid] = v;
    __syncthreads();
    #pragma unroll
    for (int off = 1; off < 128; off <<= 1) {
        int t = (tid >= off) ? s[tid - off] : 0;
        __syncthreads();
        s[tid] += t;
        __syncthreads();
    }
    if (tid < nb) g_boff[tid] = s[tid] - v;     // exclusive
}

__global__ __launch_bounds__(1024) void k_scan3() {
    int g = blockIdx.x * 1024 + threadIdx.x;
    if (g < NN) {
        int o = g_off[g] + g_boff[blockIdx.x];
        g_off[g] = o;
        g_cursor[g] = o;
    }
    if (g == 0) g_off[NN] = EE;
}

__global__ __launch_bounds__(256) void k_scatter(const int* __restrict__ ei) {
    int e = blockIdx.x * 256 + threadIdx.x;
    int d = ei[EE + e];
    int pos = atomicAdd(&g_cursor[d], 1);
    g_src_sorted[pos] = ei[e];
    g_eid_sorted[pos] = e;
}

// ---------------- GINE gather: warp per node, no atomics ----------------
__global__ __launch_bounds__(256) void k_gine_gather(const float* __restrict__ x,
                                                     const float* __restrict__ ea,
                                                     const float* __restrict__ eps) {
    int node = (blockIdx.x * 256 + threadIdx.x) >> 5;
    int lane = threadIdx.x & 31;
    if (node >= NN) return;
    const float4* x4 = (const float4*)x;
    const float4* ea4 = (const float4*)ea;

    float e1 = 1.0f + eps[0];
    float4 acc = x4[(size_t)node * 32 + lane];
    acc.x *= e1; acc.y *= e1; acc.z *= e1; acc.w *= e1;

    int o0 = g_off[node], o1 = g_off[node + 1];
    for (int base = o0; base < o1; base += 32) {
        int rem = o1 - base;
        int m = rem < 32 ? rem : 32;
        int sj = 0, ej = 0;
        if (lane < m) { sj = g_src_sorted[base + lane]; ej = g_eid_sorted[base + lane]; }
        for (int j = 0; j < m; j++) {
            int s = __shfl_sync(0xffffffffu, sj, j);
            int e = __shfl_sync(0xffffffffu, ej, j);
            float4 xs = __ldg(&x4[(size_t)s * 32 + lane]);
            float4 ev = __ldg(&ea4[(size_t)e * 32 + lane]);
            acc.x += fmaxf(xs.x + ev.x, 0.f);
            acc.y += fmaxf(xs.y + ev.y, 0.f);
            acc.z += fmaxf(xs.z + ev.z, 0.f);
            acc.w += fmaxf(xs.w + ev.w, 0.f);
        }
    }
    ((float4*)g_agg)[(size_t)node * 32 + lane] = acc;
}

// ---------------- tf32-split tensor-core GEMM machinery -------------------
#define A_LD 132      // A_s row stride (floats): banks (4*qr + qc) -> conflict-free A frags
#define W_LD 136      // W_s row stride (floats): banks (8*qc + qr) -> conflict-free B frags
#define A_FL (64 * A_LD)
#define W_FL (128 * W_LD)
#define SMEM_BYTES ((A_FL + W_FL) * 4)

__device__ __forceinline__ void split_tf32(float x, uint32_t& hi, uint32_t& lo) {
    asm("cvt.rna.tf32.f32 %0, %1;" : "=r"(hi) : "f"(x));
    float r = x - __uint_as_float(hi);
    asm("cvt.rna.tf32.f32 %0, %1;" : "=r"(lo) : "f"(r));
}

__device__ __forceinline__ void mma_tf32(float c[4], const uint32_t a[4], const uint32_t b[2]) {
    asm volatile("mma.sync.aligned.m16n8k8.row.col.f32.tf32.tf32.f32 "
                 "{%0,%1,%2,%3},{%4,%5,%6,%7},{%8,%9},{%0,%1,%2,%3};"
                 : "+f"(c[0]), "+f"(c[1]), "+f"(c[2]), "+f"(c[3])
                 : "r"(a[0]), "r"(a[1]), "r"(a[2]), "r"(a[3]), "r"(b[0]), "r"(b[1]));
}

// one 64x128x128 GEMM pass: acc += A_s @ W_s (fp32-accurate via tf32 split)
__device__ __forceinline__ void mma_stage(float c[2][4][4], const float* A_s, const float* W_s,
                                          int wm, int wn, int qr, int qc) {
    #pragma unroll 2
    for (int k0 = 0; k0 < DIM; k0 += 8) {
        uint32_t ah[2][4], al[2][4];
        #pragma unroll
        for (int i = 0; i < 2; i++) {
            int rb = wm * 32 + i * 16 + qr;
            float a0 = A_s[rb * A_LD + k0 + qc];
            float a1 = A_s[(rb + 8) * A_LD + k0 + qc];
            float a2 = A_s[rb * A_LD + k0 + 4 + qc];
            float a3 = A_s[(rb + 8) * A_LD + k0 + 4 + qc];
            split_tf32(a0, ah[i][0], al[i][0]);
            split_tf32(a1, ah[i][1], al[i][1]);
            split_tf32(a2, ah[i][2], al[i][2]);
            split_tf32(a3, ah[i][3], al[i][3]);
        }
        uint32_t bh[4][2], bl[4][2];
        #pragma unroll
        for (int j = 0; j < 4; j++) {
            int nc = wn * 32 + j * 8 + qr;
            float b0 = W_s[(k0 + qc) * W_LD + nc];
            float b1 = W_s[(k0 + 4 + qc) * W_LD + nc];
            split_tf32(b0, bh[j][0], bl[j][0]);
            split_tf32(b1, bh[j][1], bl[j][1]);
        }
        #pragma unroll
        for (int i = 0; i < 2; i++)
            #pragma unroll
            for (int j = 0; j < 4; j++) {
                mma_tf32(c[i][j], ah[i], bh[j]);   // hi*hi
                mma_tf32(c[i][j], ah[i], bl[j]);   // hi*lo
                mma_tf32(c[i][j], al[i], bh[j]);   // lo*hi
            }
    }
}

__device__ __forceinline__ void acc_init_bias(float c[2][4][4], const float* bias, int wn, int qc) {
    #pragma unroll
    for (int j = 0; j < 4; j++) {
        int col = wn * 32 + j * 8 + 2 * qc;
        float b0 = bias ? __ldg(bias + col) : 0.f;
        float b1 = bias ? __ldg(bias + col + 1) : 0.f;
        #pragma unroll
        for (int i = 0; i < 2; i++) {
            c[i][j][0] = b0; c[i][j][1] = b1; c[i][j][2] = b0; c[i][j][3] = b1;
        }
    }
}

template <bool RELU>
__device__ __forceinline__ void acc_store(const float c[2][4][4], float* A_s,
                                          int wm, int wn, int qr, int qc) {
    #pragma unroll
    for (int i = 0; i < 2; i++) {
        int row = wm * 32 + i * 16 + qr;
        #pragma unroll
        for (int j = 0; j < 4; j++) {
            int col = wn * 32 + j * 8 + 2 * qc;
            float v0 = c[i][j][0], v1 = c[i][j][1], v2 = c[i][j][2], v3 = c[i][j][3];
            if (RELU) { v0 = fmaxf(v0, 0.f); v1 = fmaxf(v1, 0.f);
                        v2 = fmaxf(v2, 0.f); v3 = fmaxf(v3, 0.f); }
            *(float2*)(A_s + row * A_LD + col)       = make_float2(v0, v1);
            *(float2*)(A_s + (row + 8) * A_LD + col) = make_float2(v2, v3);
        }
    }
}

// ---------------- fused 3-stage tensor-core GEMM (MLP + LN1 + gat proj) ----
__global__ __launch_bounds__(256, 2) void k_fused_gemm(
    const float* __restrict__ x,
    const float* __restrict__ w1, const float* __restrict__ b1,
    const float* __restrict__ w2, const float* __restrict__ b2,
    const float* __restrict__ ln1g, const float* __restrict__ ln1b,
    const float* __restrict__ gatw,
    const float* __restrict__ atts, const float* __restrict__ attd) {
    extern __shared__ float smem[];
    float* W_s = smem;            // 128 x W_LD
    float* A_s = smem + W_FL;     // 64 x A_LD

    const int t = threadIdx.x;
    const int lane = t & 31;
    const int wid = t >> 5;           // 0..7
    const int wm = wid & 1;           // 2 warps along M (32 rows each)
    const int wn = wid >> 1;          // 4 warps along N (32 cols each)
    const int qr = lane >> 2;
    const int qc = lane & 3;
    const int row0 = blockIdx.x * 64;

    // ---- stage W1 (padded) + A tile from g_agg (padded) ----
    #pragma unroll
    for (int i = 0; i < 16; i++) {
        int idx = t + 256 * i;                 // 4096 float4
        ((float4*)W_s)[(idx >> 5) * (W_LD / 4) + (idx & 31)] = ((const float4*)w1)[idx];
    }
    #pragma unroll
    for (int i = 0; i < 8; i++) {
        int idx = t + 256 * i;                 // 2048 float4
        int r = idx >> 5;
        float4 v = (row0 + r < NN) ? ((const float4*)g_agg)[(size_t)(row0 + r) * 32 + (idx & 31)]
                                   : make_float4(0.f, 0.f, 0.f, 0.f);
        ((float4*)A_s)[r * (A_LD / 4) + (idx & 31)] = v;
    }
    __syncthreads();

    float acc[2][4][4];

    // ---- GEMM1: relu(agg@W1 + b1) -> A_s ----
    acc_init_bias(acc, b1, wn, qc);
    mma_stage(acc, A_s, W_s, wm, wn, qr, qc);
    __syncthreads();
    acc_store<true>(acc, A_s, wm, wn, qr, qc);
    #pragma unroll
    for (int i = 0; i < 16; i++) {
        int idx = t + 256 * i;
        ((float4*)W_s)[(idx >> 5) * (W_LD / 4) + (idx & 31)] = ((const float4*)w2)[idx];
    }
    __syncthreads();

    // ---- GEMM2: .@W2 + b2 ----
    acc_init_bias(acc, b2, wn, qc);
    mma_stage(acc, A_s, W_s, wm, wn, qr, qc);
    __syncthreads();
    acc_store<false>(acc, A_s, wm, wn, qr, qc);
    __syncthreads();

    // ---- LN1 row pass: relu -> LN -> +x, write g_h and A_s; also stage gat_w
    {
        float4 g4 = ((const float4*)ln1g)[lane];
        float4 bb = ((const float4*)ln1b)[lane];
        #pragma unroll
        for (int rr = 0; rr < 8; rr++) {
            int r = wid * 8 + rr;
            int row = row0 + r;
            float4 v = ((float4*)(A_s + r * A_LD))[lane];
            v.x = fmaxf(v.x, 0.f); v.y = fmaxf(v.y, 0.f);
            v.z = fmaxf(v.z, 0.f); v.w = fmaxf(v.w, 0.f);
            float s = v.x + v.y + v.z + v.w;
            #pragma unroll
            for (int o = 16; o; o >>= 1) s += __shfl_xor_sync(0xffffffffu, s, o);
            float mu = s * (1.0f / DIM);
            float dx = v.x - mu, dy = v.y - mu, dz = v.z - mu, dw = v.w - mu;
            float ss = dx * dx + dy * dy + dz * dz + dw * dw;
            #pragma unroll
            for (int o = 16; o; o >>= 1) ss += __shfl_xor_sync(0xffffffffu, ss, o);
            float inv = rsqrtf(ss * (1.0f / DIM) + 1e-5f);
            float4 res = (row < NN) ? ((const float4*)x)[(size_t)row * 32 + lane]
                                    : make_float4(0.f, 0.f, 0.f, 0.f);
            float4 o4;
            o4.x = dx * inv * g4.x + bb.x + res.x;
            o4.y = dy * inv * g4.y + bb.y + res.y;
            o4.z = dz * inv * g4.z + bb.z + res.z;
            o4.w = dw * inv * g4.w + bb.w + res.w;
            if (row < NN) ((float4*)g_h)[(size_t)row * 32 + lane] = o4;
            ((float4*)(A_s + r * A_LD))[lane] = o4;
        }
        #pragma unroll
        for (int i = 0; i < 16; i++) {
            int idx = t + 256 * i;
            ((float4*)W_s)[(idx >> 5) * (W_LD / 4) + (idx & 31)] = ((const float4*)gatw)[idx];
        }
    }
    __syncthreads();

    // ---- GEMM3: h@gat_w -> xp + attention coefficients ----
    acc_init_bias(acc, nullptr, wn, qc);
    mma_stage(acc, A_s, W_s, wm, wn, qr, qc);
    __syncthreads();
    acc_store<false>(acc, A_s, wm, wn, qr, qc);
    __syncthreads();

    {
        float4 as = ((const float4*)atts)[lane];
        float4 ad = ((const float4*)attd)[lane];
        #pragma unroll
        for (int rr = 0; rr < 8; rr++) {
            int r = wid * 8 + rr;
            int row = row0 + r;
            float4 v = ((float4*)(A_s + r * A_LD))[lane];
            float ps = v.x * as.x + v.y * as.y + v.z * as.z + v.w * as.w;
            float pd = v.x * ad.x + v.y * ad.y + v.z * ad.z + v.w * ad.w;
            #pragma unroll
            for (int o = 4; o; o >>= 1) {
                ps += __shfl_down_sync(0xffffffffu, ps, o, 8);
                pd += __shfl_down_sync(0xffffffffu, pd, o, 8);
            }
            if (row < NN) {
                ((float4*)g_xp)[(size_t)row * 32 + lane] = v;
                if ((lane & 7) == 0) {
                    g_asrc[row * HEADS + (lane >> 3)] = ps;
                    g_adst[row * HEADS + (lane >> 3)] = pd;
                }
            }
        }
    }
}

// ---------------- GAT gather: warp per node, fused softmax+norm+LN2+resid --
__global__ __launch_bounds__(256) void k_gat_gather(const float* __restrict__ gat_b,
                                                    const float* __restrict__ ln2g,
                                                    const float* __restrict__ ln2b,
                                                    float* __restrict__ outp) {
    int node = (blockIdx.x * 256 + threadIdx.x) >> 5;
    int lane = threadIdx.x & 31;
    if (node >= NN) return;
    const float4* xp4 = (const float4*)g_xp;
    int h = lane >> 3;

    float adst_d = g_adst[node * HEADS + h];
    // self loop
    float l = g_asrc[node * HEADS + h] + adst_d;
    l = (l > 0.f) ? l : 0.2f * l;
    float w = __expf(l);
    float wsum = w;
    float4 xv = xp4[(size_t)node * 32 + lane];
    float4 acc = make_float4(w * xv.x, w * xv.y, w * xv.z, w * xv.w);

    int o0 = g_off[node], o1 = g_off[node + 1];
    for (int base = o0; base < o1; base += 32) {
        int rem = o1 - base;
        int m = rem < 32 ? rem : 32;
        int sj = 0;
        if (lane < m) sj = g_src_sorted[base + lane];
        for (int j = 0; j < m; j++) {
            int s = __shfl_sync(0xffffffffu, sj, j);
            float l2 = g_asrc[s * HEADS + h] + adst_d;
            l2 = (l2 > 0.f) ? l2 : 0.2f * l2;
            float aw = __expf(l2);
            wsum += aw;
            float4 v = __ldg(&xp4[(size_t)s * 32 + lane]);
            acc.x = fmaf(aw, v.x, acc.x);
            acc.y = fmaf(aw, v.y, acc.y);
            acc.z = fmaf(aw, v.z, acc.z);
            acc.w = fmaf(aw, v.w, acc.w);
        }
    }

    float inv_s = 1.0f / (wsum + 1e-16f);
    float4 gb = ((const float4*)gat_b)[lane];
    float4 v;
    v.x = fmaxf(acc.x * inv_s + gb.x, 0.f);
    v.y = fmaxf(acc.y * inv_s + gb.y, 0.f);
    v.z = fmaxf(acc.z * inv_s + gb.z, 0.f);
    v.w = fmaxf(acc.w * inv_s + gb.w, 0.f);
    float s = v.x + v.y + v.z + v.w;
    #pragma unroll
    for (int o = 16; o; o >>= 1) s += __shfl_xor_sync(0xffffffffu, s, o);
    float mu = s * (1.0f / DIM);
    float dx = v.x - mu, dy = v.y - mu, dz = v.z - mu, dw = v.w - mu;
    float ss = dx * dx + dy * dy + dz * dz + dw * dw;
    #pragma unroll
    for (int o = 16; o; o >>= 1) ss += __shfl_xor_sync(0xffffffffu, ss, o);
    float inv = rsqrtf(ss * (1.0f / DIM) + 1e-5f);
    float4 g = ((const float4*)ln2g)[lane];
    float4 b = ((const float4*)ln2b)[lane];
    float4 hres = ((const float4*)g_h)[(size_t)node * 32 + lane];
    float4 o4;
    o4.x = dx * inv * g.x + b.x + hres.x;
    o4.y = dy * inv * g.y + b.y + hres.y;
    o4.z = dz * inv * g.z + b.z + hres.z;
    o4.w = dw * inv * g.w + b.w + hres.w;
    ((float4*)outp)[(size_t)node * 32 + lane] = o4;
}

// ---------------- launch ----------------
extern "C" void kernel_launch(void* const* d_in, const int* in_sizes, int n_in,
                              void* d_out, int out_size) {
    const float* x      = (const float*)d_in[0];
    const int*   ei     = (const int*)d_in[1];
    const float* ea     = (const float*)d_in[2];
    const float* eps    = (const float*)d_in[3];
    const float* w1     = (const float*)d_in[4];
    const float* b1     = (const float*)d_in[5];
    const float* w2     = (const float*)d_in[6];
    const float* b2     = (const float*)d_in[7];
    const float* ln1_g  = (const float*)d_in[8];
    const float* ln1_b  = (const float*)d_in[9];
    const float* gat_w  = (const float*)d_in[10];
    const float* att_s  = (const float*)d_in[11];
    const float* att_d  = (const float*)d_in[12];
    const float* gat_b  = (const float*)d_in[13];
    const float* ln2_g  = (const float*)d_in[14];
    const float* ln2_b  = (const float*)d_in[15];
    float* outp = (float*)d_out;

    cudaFuncSetAttribute(k_fused_gemm, cudaFuncAttributeMaxDynamicSharedMemorySize, SMEM_BYTES);

    const int scan_blocks = (NN + 1023) / 1024;   // 98
    const int edge_blocks = EE / 256;             // 6250
    const int node_blocks = (NN * 32) / 256;      // 12500
    const int gemm_blocks = (NN + 63) / 64;       // 1563

    // CSR build (by dst)
    k_zero_deg<<<scan_blocks, 1024>>>();
    k_hist<<<edge_blocks, 256>>>(ei);
    k_scan1<<<scan_blocks, 1024>>>();
    k_scan2<<<1, 128>>>(scan_blocks);
    k_scan3<<<scan_blocks, 1024>>>();
    k_scatter<<<edge_blocks, 256>>>(ei);

    // GINE aggregation (gather, fused (1+eps)*x)
    k_gine_gather<<<node_blocks, 256>>>(x, ea, eps);

    // MLP + LN1 + residual + gat projection + attention coefficients (tf32x2 MMA)
    k_fused_gemm<<<gemm_blocks, 256, SMEM_BYTES>>>(x, w1, b1, w2, b2,
                                                   ln1_g, ln1_b, gat_w, att_s, att_d);

    // GAT aggregation (gather, fused softmax + bias + relu + LN2 + residual)
    k_gat_gather<<<node_blocks, 256>>>(gat_b, ln2_g, ln2_b, outp);
}

// round 16
// speedup vs baseline: 1.6153x; 1.0004x over previous
#include <cuda_runtime.h>
#include <cuda_bf16.h>
#include <math.h>
#include <stdint.h>

#define NN 100000
#define EE 1600000
#define DIM 128
#define HEADS 4
#define HC 32

// ---------------- device scratch ----------------
__device__ float g_agg[NN * DIM];   // (1+eps)*x + sum relu(x[src]+ea)
__device__ float g_h[NN * DIM];     // LN1(relu(MLP)) + x
__device__ float g_xp[NN * DIM];    // h @ gat_w
__device__ float g_asrc[NN * HEADS];
__device__ float g_adst[NN * HEADS];

// CSR by dst
__device__ int g_deg[NN];
__device__ int g_off[NN + 1];
__device__ int g_cursor[NN];
__device__ int g_bsum[128];
__device__ int g_boff[128];
__device__ int g_src_sorted[EE];
__device__ int g_eid_sorted[EE];

// ---------------- CSR build ----------------
__global__ __launch_bounds__(1024) void k_zero_deg() {
    int g = blockIdx.x * 1024 + threadIdx.x;
    if (g < NN) g_deg[g] = 0;
}

__global__ __launch_bounds__(256) void k_hist(const int* __restrict__ ei) {
    int e = blockIdx.x * 256 + threadIdx.x;   // grid sized exactly EE/256
    atomicAdd(&g_deg[ei[EE + e]], 1);
}

__global__ __launch_bounds__(1024) void k_scan1() {
    __shared__ int s[1024];
    int tid = threadIdx.x;
    int g = blockIdx.x * 1024 + tid;
    int v = (g < NN) ? g_deg[g] : 0;
    s[tid] = v;
    __syncthreads();
    #pragma unroll
    for (int off = 1; off < 1024; off <<= 1) {
        int t = (tid >= off) ? s[tid - off] : 0;
        __syncthreads();
        s[tid] += t;
        __syncthreads();
    }
    if (g < NN) g_off[g] = s[tid] - v;          // exclusive, block-local
    if (tid == 1023) g_bsum[blockIdx.x] = s[1023];
}

__global__ __launch_bounds__(128) void k_scan2(int nb) {
    __shared__ int s[128];
    int tid = threadIdx.x;
    int v = (tid < nb) ? g_bsum[tid] : 0;
    s[tid] = v;
    __syncthreads();
    #pragma unroll
    for (int off = 1; off < 128; off <<= 1) {
        int t = (tid >= off) ? s[tid - off] : 0;
        __syncthreads();
        s[tid] += t;
        __syncthreads();
    }
    if (tid < nb) g_boff[tid] = s[tid] - v;     // exclusive
}

__global__ __launch_bounds__(1024) void k_scan3() {
    int g = blockIdx.x * 1024 + threadIdx.x;
    if (g < NN) {
        int o = g_off[g] + g_boff[blockIdx.x];
        g_off[g] = o;
        g_cursor[g] = o;
    }
    if (g == 0) g_off[NN] = EE;
}

__global__ __launch_bounds__(256) void k_scatter(const int* __restrict__ ei) {
    int e = blockIdx.x * 256 + threadIdx.x;
    int d = ei[EE + e];
    int pos = atomicAdd(&g_cursor[d], 1);
    g_src_sorted[pos] = ei[e];
    g_eid_sorted[pos] = e;
}

// ---------------- GINE gather: warp per node, no atomics ----------------
__global__ __launch_bounds__(256) void k_gine_gather(const float* __restrict__ x,
                                                     const float* __restrict__ ea,
                                                     const float* __restrict__ eps) {
    int node = (blockIdx.x * 256 + threadIdx.x) >> 5;
    int lane = threadIdx.x & 31;
    if (node >= NN) return;
    const float4* x4 = (const float4*)x;
    const float4* ea4 = (const float4*)ea;

    float e1 = 1.0f + eps[0];
    float4 acc = x4[(size_t)node * 32 + lane];
    acc.x *= e1; acc.y *= e1; acc.z *= e1; acc.w *= e1;

    int o0 = g_off[node], o1 = g_off[node + 1];
    for (int base = o0; base < o1; base += 32) {
        int rem = o1 - base;
        int m = rem < 32 ? rem : 32;
        int sj = 0, ej = 0;
        if (lane < m) { sj = g_src_sorted[base + lane]; ej = g_eid_sorted[base + lane]; }
        for (int j = 0; j < m; j++) {
            int s = __shfl_sync(0xffffffffu, sj, j);
            int e = __shfl_sync(0xffffffffu, ej, j);
            float4 xs = __ldg(&x4[(size_t)s * 32 + lane]);
            float4 ev = __ldg(&ea4[(size_t)e * 32 + lane]);
            acc.x += fmaxf(xs.x + ev.x, 0.f);
            acc.y += fmaxf(xs.y + ev.y, 0.f);
            acc.z += fmaxf(xs.z + ev.z, 0.f);
            acc.w += fmaxf(xs.w + ev.w, 0.f);
        }
    }
    ((float4*)g_agg)[(size_t)node * 32 + lane] = acc;
}

// ---------------- tf32-split tensor-core GEMM machinery -------------------
#define A_LD 132      // A_s row stride (floats): banks (4*qr + qc) -> conflict-free A frags
#define W_LD 136      // W_s row stride (floats): banks (8*qc + qr) -> conflict-free B frags
#define A_FL (64 * A_LD)
#define W_FL (128 * W_LD)
#define SMEM_BYTES ((A_FL + W_FL) * 4)

__device__ __forceinline__ void split_tf32(float x, uint32_t& hi, uint32_t& lo) {
    asm("cvt.rna.tf32.f32 %0, %1;" : "=r"(hi) : "f"(x));
    float r = x - __uint_as_float(hi);
    asm("cvt.rna.tf32.f32 %0, %1;" : "=r"(lo) : "f"(r));
}

__device__ __forceinline__ void mma_tf32(float c[4], const uint32_t a[4], const uint32_t b[2]) {
    asm volatile("mma.sync.aligned.m16n8k8.row.col.f32.tf32.tf32.f32 "
                 "{%0,%1,%2,%3},{%4,%5,%6,%7},{%8,%9},{%0,%1,%2,%3};"
                 : "+f"(c[0]), "+f"(c[1]), "+f"(c[2]), "+f"(c[3])
                 : "r"(a[0]), "r"(a[1]), "r"(a[2]), "r"(a[3]), "r"(b[0]), "r"(b[1]));
}

// one 64x128x128 GEMM pass: acc += A_s @ W_s (fp32-accurate via tf32 split)
__device__ __forceinline__ void mma_stage(float c[2][4][4], const float* A_s, const float* W_s,
                                          int wm, int wn, int qr, int qc) {
    #pragma unroll 2
    for (int k0 = 0; k0 < DIM; k0 += 8) {
        uint32_t ah[2][4], al[2][4];
        #pragma unroll
        for (int i = 0; i < 2; i++) {
            int rb = wm * 32 + i * 16 + qr;
            float a0 = A_s[rb * A_LD + k0 + qc];
            float a1 = A_s[(rb + 8) * A_LD + k0 + qc];
            float a2 = A_s[rb * A_LD + k0 + 4 + qc];
            float a3 = A_s[(rb + 8) * A_LD + k0 + 4 + qc];
            split_tf32(a0, ah[i][0], al[i][0]);
            split_tf32(a1, ah[i][1], al[i][1]);
            split_tf32(a2, ah[i][2], al[i][2]);
            split_tf32(a3, ah[i][3], al[i][3]);
        }
        uint32_t bh[4][2], bl[4][2];
        #pragma unroll
        for (int j = 0; j < 4; j++) {
            int nc = wn * 32 + j * 8 + qr;
            float b0 = W_s[(k0 + qc) * W_LD + nc];
            float b1 = W_s[(k0 + 4 + qc) * W_LD + nc];
            split_tf32(b0, bh[j][0], bl[j][0]);
            split_tf32(b1, bh[j][1], bl[j][1]);
        }
        #pragma unroll
        for (int i = 0; i < 2; i++)
            #pragma unroll
            for (int j = 0; j < 4; j++) {
                mma_tf32(c[i][j], ah[i], bh[j]);   // hi*hi
                mma_tf32(c[i][j], ah[i], bl[j]);   // hi*lo
                mma_tf32(c[i][j], al[i], bh[j]);   // lo*hi
            }
    }
}

__device__ __forceinline__ void acc_init_bias(float c[2][4][4], const float* bias, int wn, int qc) {
    #pragma unroll
    for (int j = 0; j < 4; j++) {
        int col = wn * 32 + j * 8 + 2 * qc;
        float b0 = bias ? __ldg(bias + col) : 0.f;
        float b1 = bias ? __ldg(bias + col + 1) : 0.f;
        #pragma unroll
        for (int i = 0; i < 2; i++) {
            c[i][j][0] = b0; c[i][j][1] = b1; c[i][j][2] = b0; c[i][j][3] = b1;
        }
    }
}

template <bool RELU>
__device__ __forceinline__ void acc_store(const float c[2][4][4], float* A_s,
                                          int wm, int wn, int qr, int qc) {
    #pragma unroll
    for (int i = 0; i < 2; i++) {
        int row = wm * 32 + i * 16 + qr;
        #pragma unroll
        for (int j = 0; j < 4; j++) {
            int col = wn * 32 + j * 8 + 2 * qc;
            float v0 = c[i][j][0], v1 = c[i][j][1], v2 = c[i][j][2], v3 = c[i][j][3];
            if (RELU) { v0 = fmaxf(v0, 0.f); v1 = fmaxf(v1, 0.f);
                        v2 = fmaxf(v2, 0.f); v3 = fmaxf(v3, 0.f); }
            *(float2*)(A_s + row * A_LD + col)       = make_float2(v0, v1);
            *(float2*)(A_s + (row + 8) * A_LD + col) = make_float2(v2, v3);
        }
    }
}

// ---------------- fused 3-stage tensor-core GEMM (MLP + LN1 + gat proj) ----
__global__ __launch_bounds__(256, 2) void k_fused_gemm(
    const float* __restrict__ x,
    const float* __restrict__ w1, const float* __restrict__ b1,
    const float* __restrict__ w2, const float* __restrict__ b2,
    const float* __restrict__ ln1g, const float* __restrict__ ln1b,
    const float* __restrict__ gatw,
    const float* __restrict__ atts, const float* __restrict__ attd) {
    extern __shared__ float smem[];
    float* W_s = smem;            // 128 x W_LD
    float* A_s = smem + W_FL;     // 64 x A_LD

    const int t = threadIdx.x;
    const int lane = t & 31;
    const int wid = t >> 5;           // 0..7
    const int wm = wid & 1;           // 2 warps along M (32 rows each)
    const int wn = wid >> 1;          // 4 warps along N (32 cols each)
    const int qr = lane >> 2;
    const int qc = lane & 3;
    const int row0 = blockIdx.x * 64;

    // ---- stage W1 (padded) + A tile from g_agg (padded) ----
    #pragma unroll
    for (int i = 0; i < 16; i++) {
        int idx = t + 256 * i;                 // 4096 float4
        ((float4*)W_s)[(idx >> 5) * (W_LD / 4) + (idx & 31)] = ((const float4*)w1)[idx];
    }
    #pragma unroll
    for (int i = 0; i < 8; i++) {
        int idx = t + 256 * i;                 // 2048 float4
        int r = idx >> 5;
        float4 v = (row0 + r < NN) ? ((const float4*)g_agg)[(size_t)(row0 + r) * 32 + (idx & 31)]
                                   : make_float4(0.f, 0.f, 0.f, 0.f);
        ((float4*)A_s)[r * (A_LD / 4) + (idx & 31)] = v;
    }
    __syncthreads();

    float acc[2][4][4];

    // ---- GEMM1: relu(agg@W1 + b1) -> A_s ----
    acc_init_bias(acc, b1, wn, qc);
    mma_stage(acc, A_s, W_s, wm, wn, qr, qc);
    __syncthreads();
    acc_store<true>(acc, A_s, wm, wn, qr, qc);
    #pragma unroll
    for (int i = 0; i < 16; i++) {
        int idx = t + 256 * i;
        ((float4*)W_s)[(idx >> 5) * (W_LD / 4) + (idx & 31)] = ((const float4*)w2)[idx];
    }
    __syncthreads();

    // ---- GEMM2: .@W2 + b2 ----
    acc_init_bias(acc, b2, wn, qc);
    mma_stage(acc, A_s, W_s, wm, wn, qr, qc);
    __syncthreads();
    acc_store<false>(acc, A_s, wm, wn, qr, qc);
    __syncthreads();

    // ---- LN1 row pass: relu -> LN -> +x, write g_h and A_s; also stage gat_w
    {
        float4 g4 = ((const float4*)ln1g)[lane];
        float4 bb = ((const float4*)ln1b)[lane];
        #pragma unroll
        for (int rr = 0; rr < 8; rr++) {
            int r = wid * 8 + rr;
            int row = row0 + r;
            float4 v = ((float4*)(A_s + r * A_LD))[lane];
            v.x = fmaxf(v.x, 0.f); v.y = fmaxf(v.y, 0.f);
            v.z = fmaxf(v.z, 0.f); v.w = fmaxf(v.w, 0.f);
            float s = v.x + v.y + v.z + v.w;
            #pragma unroll
            for (int o = 16; o; o >>= 1) s += __shfl_xor_sync(0xffffffffu, s, o);
            float mu = s * (1.0f / DIM);
            float dx = v.x - mu, dy = v.y - mu, dz = v.z - mu, dw = v.w - mu;
            float ss = dx * dx + dy * dy + dz * dz + dw * dw;
            #pragma unroll
            for (int o = 16; o; o >>= 1) ss += __shfl_xor_sync(0xffffffffu, ss, o);
            float inv = rsqrtf(ss * (1.0f / DIM) + 1e-5f);
            float4 res = (row < NN) ? ((const float4*)x)[(size_t)row * 32 + lane]
                                    : make_float4(0.f, 0.f, 0.f, 0.f);
            float4 o4;
            o4.x = dx * inv * g4.x + bb.x + res.x;
            o4.y = dy * inv * g4.y + bb.y + res.y;
            o4.z = dz * inv * g4.z + bb.z + res.z;
            o4.w = dw * inv * g4.w + bb.w + res.w;
            if (row < NN) ((float4*)g_h)[(size_t)row * 32 + lane] = o4;
            ((float4*)(A_s + r * A_LD))[lane] = o4;
        }
        #pragma unroll
        for (int i = 0; i < 16; i++) {
            int idx = t + 256 * i;
            ((float4*)W_s)[(idx >> 5) * (W_LD / 4) + (idx & 31)] = ((const float4*)gatw)[idx];
        }
    }
    __syncthreads();

    // ---- GEMM3: h@gat_w -> xp + attention coefficients ----
    acc_init_bias(acc, nullptr, wn, qc);
    mma_stage(acc, A_s, W_s, wm, wn, qr, qc);
    __syncthreads();
    acc_store<false>(acc, A_s, wm, wn, qr, qc);
    __syncthreads();

    {
        float4 as = ((const float4*)atts)[lane];
        float4 ad = ((const float4*)attd)[lane];
        #pragma unroll
        for (int rr = 0; rr < 8; rr++) {
            int r = wid * 8 + rr;
            int row = row0 + r;
            float4 v = ((float4*)(A_s + r * A_LD))[lane];
            float ps = v.x * as.x + v.y * as.y + v.z * as.z + v.w * as.w;
            float pd = v.x * ad.x + v.y * ad.y + v.z * ad.z + v.w * ad.w;
            #pragma unroll
            for (int o = 4; o; o >>= 1) {
                ps += __shfl_down_sync(0xffffffffu, ps, o, 8);
                pd += __shfl_down_sync(0xffffffffu, pd, o, 8);
            }
            if (row < NN) {
                ((float4*)g_xp)[(size_t)row * 32 + lane] = v;
                if ((lane & 7) == 0) {
                    g_asrc[row * HEADS + (lane >> 3)] = ps;
                    g_adst[row * HEADS + (lane >> 3)] = pd;
                }
            }
        }
    }
}

// ---------------- GAT gather: warp per node, fused softmax+norm+LN2+resid --
__global__ __launch_bounds__(256) void k_gat_gather(const float* __restrict__ gat_b,
                                                    const float* __restrict__ ln2g,
                                                    const float* __restrict__ ln2b,
                                                    float* __restrict__ outp) {
    int node = (blockIdx.x * 256 + threadIdx.x) >> 5;
    int lane = threadIdx.x & 31;
    if (node >= NN) return;
    const float4* xp4 = (const float4*)g_xp;
    int h = lane >> 3;

    float adst_d = g_adst[node * HEADS + h];
    // self loop
    float l = g_asrc[node * HEADS + h] + adst_d;
    l = (l > 0.f) ? l : 0.2f * l;
    float w = __expf(l);
    float wsum = w;
    float4 xv = xp4[(size_t)node * 32 + lane];
    float4 acc = make_float4(w * xv.x, w * xv.y, w * xv.z, w * xv.w);

    int o0 = g_off[node], o1 = g_off[node + 1];
    for (int base = o0; base < o1; base += 32) {
        int rem = o1 - base;
        int m = rem < 32 ? rem : 32;
        int sj = 0;
        if (lane < m) sj = g_src_sorted[base + lane];
        for (int j = 0; j < m; j++) {
            int s = __shfl_sync(0xffffffffu, sj, j);
            float l2 = g_asrc[s * HEADS + h] + adst_d;
            l2 = (l2 > 0.f) ? l2 : 0.2f * l2;
            float aw = __expf(l2);
            wsum += aw;
            float4 v = __ldg(&xp4[(size_t)s * 32 + lane]);
            acc.x = fmaf(aw, v.x, acc.x);
            acc.y = fmaf(aw, v.y, acc.y);
            acc.z = fmaf(aw, v.z, acc.z);
            acc.w = fmaf(aw, v.w, acc.w);
        }
    }

    float inv_s = 1.0f / (wsum + 1e-16f);
    float4 gb = ((const float4*)gat_b)[lane];
    float4 v;
    v.x = fmaxf(acc.x * inv_s + gb.x, 0.f);
    v.y = fmaxf(acc.y * inv_s + gb.y, 0.f);
    v.z = fmaxf(acc.z * inv_s + gb.z, 0.f);
    v.w = fmaxf(acc.w * inv_s + gb.w, 0.f);
    float s = v.x + v.y + v.z + v.w;
    #pragma unroll
    for (int o = 16; o; o >>= 1) s += __shfl_xor_sync(0xffffffffu, s, o);
    float mu = s * (1.0f / DIM);
    float dx = v.x - mu, dy = v.y - mu, dz = v.z - mu, dw = v.w - mu;
    float ss = dx * dx + dy * dy + dz * dz + dw * dw;
    #pragma unroll
    for (int o = 16; o; o >>= 1) ss += __shfl_xor_sync(0xffffffffu, ss, o);
    float inv = rsqrtf(ss * (1.0f / DIM) + 1e-5f);
    float4 g = ((const float4*)ln2g)[lane];
    float4 b = ((const float4*)ln2b)[lane];
    float4 hres = ((const float4*)g_h)[(size_t)node * 32 + lane];
    float4 o4;
    o4.x = dx * inv * g.x + b.x + hres.x;
    o4.y = dy * inv * g.y + b.y + hres.y;
    o4.z = dz * inv * g.z + b.z + hres.z;
    o4.w = dw * inv * g.w + b.w + hres.w;
    ((float4*)outp)[(size_t)node * 32 + lane] = o4;
}

// ---------------- launch ----------------
extern "C" void kernel_launch(void* const* d_in, const int* in_sizes, int n_in,
                              void* d_out, int out_size) {
    const float* x      = (const float*)d_in[0];
    const int*   ei     = (const int*)d_in[1];
    const float* ea     = (const float*)d_in[2];
    const float* eps    = (const float*)d_in[3];
    const float* w1     = (const float*)d_in[4];
    const float* b1     = (const float*)d_in[5];
    const float* w2     = (const float*)d_in[6];
    const float* b2     = (const float*)d_in[7];
    const float* ln1_g  = (const float*)d_in[8];
    const float* ln1_b  = (const float*)d_in[9];
    const float* gat_w  = (const float*)d_in[10];
    const float* att_s  = (const float*)d_in[11];
    const float* att_d  = (const float*)d_in[12];
    const float* gat_b  = (const float*)d_in[13];
    const float* ln2_g  = (const float*)d_in[14];
    const float* ln2_b  = (const float*)d_in[15];
    float* outp = (float*)d_out;

    cudaFuncSetAttribute(k_fused_gemm, cudaFuncAttributeMaxDynamicSharedMemorySize, SMEM_BYTES);

    const int scan_blocks = (NN + 1023) / 1024;   // 98
    const int edge_blocks = EE / 256;             // 6250
    const int node_blocks = (NN * 32) / 256;      // 12500
    const int gemm_blocks = (NN + 63) / 64;       // 1563

    // CSR build (by dst)
    k_zero_deg<<<scan_blocks, 1024>>>();
    k_hist<<<edge_blocks, 256>>>(ei);
    k_scan1<<<scan_blocks, 1024>>>();
    k_scan2<<<1, 128>>>(scan_blocks);
    k_scan3<<<scan_blocks, 1024>>>();
    k_scatter<<<edge_blocks, 256>>>(ei);

    // GINE aggregation (gather, fused (1+eps)*x)
    k_gine_gather<<<node_blocks, 256>>>(x, ea, eps);

    // MLP + LN1 + residual + gat projection + attention coefficients (tf32x2 MMA)
    k_fused_gemm<<<gemm_blocks, 256, SMEM_BYTES>>>(x, w1, b1, w2, b2,
                                                   ln1_g, ln1_b, gat_w, att_s, att_d);

    // GAT aggregation (gather, fused softmax + bias + relu + LN2 + residual)
    k_gat_gather<<<node_blocks, 256>>>(gat_b, ln2_g, ln2_b, outp);
}